// round 10
// baseline (speedup 1.0000x reference)
#include <cuda_runtime.h>
#include <math.h>
#include <cstdint>

// Problem constants
#define BB 4
#define TT 2048
#define CC 2048
#define HH 16
#define KVH 4
#define GG 4
#define DD 128
#define MROWS (BB*TT)          // 8192

// ---------------- scratch (device globals; allocation is forbidden) --------
__device__ float  g_q [(size_t)MROWS * (HH*DD)];
__device__ float  g_k [(size_t)MROWS * (KVH*DD)];
__device__ float  g_v [(size_t)MROWS * (KVH*DD)];
__device__ float  g_ao[(size_t)MROWS * (HH*DD)];
__device__ float2 g_cs[TT][64];                    // cos/sin(t * 10000^(-p/64))

// ---------------------------------------------------------------------------
// Angle table: fp32-rounded angle exactly as jnp would, then double trig.
// ---------------------------------------------------------------------------
__global__ void init_tables_kernel()
{
    int idx = blockIdx.x * blockDim.x + threadIdx.x;   // t*64 + p
    if (idx >= TT * 64) return;
    int t = idx >> 6;
    int p = idx & 63;

    double ex   = (double)p / 64.0;
    float  invf = (float)pow(10000.0, -ex);
    float  ang  = (float)t * invf;
    double c, s;
    sincos((double)ang, &c, &s);
    g_cs[t][p] = make_float2((float)c, (float)s);
}

// ---------------------------------------------------------------------------
// SGEMM with fused half-split RoPE epilogue — REVERSED rotation direction
// (sin negated), as identified by the round-9 probe:
//   out[p]    =  a0 * cos + a1 * sin
//   out[p+64] =  a1 * cos - a0 * sin
// C[M,N] = A[M,K] @ B[K,N], fp32. 128x128 tile, BK=8, 256 threads, 8x8/thread.
// ---------------------------------------------------------------------------
__global__ __launch_bounds__(256) void sgemm128_rope_kernel(
    const float* __restrict__ A, const float* __restrict__ B,
    float* __restrict__ C, int M, int N, int K, int rope)
{
    __shared__ float As[8][128];
    __shared__ float Bs[8][128];

    const int tid = threadIdx.x;
    const int tx = tid & 15;
    const int ty = tid >> 4;
    const int bm = blockIdx.y * 128;
    const int bn = blockIdx.x * 128;

    const float* Ap = A + (size_t)bm * K;
    const float* Bp = B + bn;

    const int a_m = tid >> 1;
    const int a_k = (tid & 1) * 4;
    const int b_k = tid >> 5;
    const int b_n = (tid & 31) * 4;

    float acc[8][8];
#pragma unroll
    for (int i = 0; i < 8; i++)
#pragma unroll
        for (int j = 0; j < 8; j++) acc[i][j] = 0.f;

    for (int k0 = 0; k0 < K; k0 += 8) {
        float4 av = *(const float4*)(Ap + (size_t)a_m * K + k0 + a_k);
        float4 bv = *(const float4*)(Bp + (size_t)(k0 + b_k) * N + b_n);
        __syncthreads();
        As[a_k + 0][a_m] = av.x;
        As[a_k + 1][a_m] = av.y;
        As[a_k + 2][a_m] = av.z;
        As[a_k + 3][a_m] = av.w;
        *(float4*)&Bs[b_k][b_n] = bv;
        __syncthreads();

#pragma unroll
        for (int kk = 0; kk < 8; kk++) {
            float4 a0 = *(const float4*)&As[kk][ty * 4];
            float4 a1 = *(const float4*)&As[kk][64 + ty * 4];
            float4 b0 = *(const float4*)&Bs[kk][tx * 4];
            float4 b1 = *(const float4*)&Bs[kk][64 + tx * 4];
            float af[8] = {a0.x,a0.y,a0.z,a0.w,a1.x,a1.y,a1.z,a1.w};
            float bf[8] = {b0.x,b0.y,b0.z,b0.w,b1.x,b1.y,b1.z,b1.w};
#pragma unroll
            for (int i = 0; i < 8; i++)
#pragma unroll
                for (int j = 0; j < 8; j++)
                    acc[i][j] += af[i] * bf[j];
        }
    }

    if (rope) {
#pragma unroll
        for (int ih = 0; ih < 2; ih++) {
#pragma unroll
            for (int i = 0; i < 4; i++) {
                int r = bm + ih * 64 + ty * 4 + i;
                int t = r & (TT - 1);
#pragma unroll
                for (int j = 0; j < 4; j++) {
                    int p = tx * 4 + j;
                    float2 cs = g_cs[t][p];
                    float a0 = acc[ih*4+i][j];
                    float a1 = acc[ih*4+i][4+j];
                    // reversed rotation (validated round 9)
                    acc[ih*4+i][j]   = a0 * cs.x + a1 * cs.y;
                    acc[ih*4+i][4+j] = a1 * cs.x - a0 * cs.y;
                }
            }
        }
    }

#pragma unroll
    for (int ih = 0; ih < 2; ih++) {
#pragma unroll
        for (int i = 0; i < 4; i++) {
            int r = bm + ih * 64 + ty * 4 + i;
            float* crow = C + (size_t)r * N + bn;
            float4 v0 = make_float4(acc[ih*4+i][0], acc[ih*4+i][1], acc[ih*4+i][2], acc[ih*4+i][3]);
            float4 v1 = make_float4(acc[ih*4+i][4], acc[ih*4+i][5], acc[ih*4+i][6], acc[ih*4+i][7]);
            *(float4*)(crow + tx * 4)      = v0;
            *(float4*)(crow + 64 + tx * 4) = v1;
        }
    }
}

// ---------------------------------------------------------------------------
// Attention (causal, GQA), warp-private formulation.
// Block: 256 threads = 8 warps; one (b, h, 64-query-row tile) per block.
// smem: Q[64][128] | K[64][129] | V[64][128] | P[64][64]
// ---------------------------------------------------------------------------
__global__ __launch_bounds__(256) void attn_kernel(
    const float* __restrict__ q, const float* __restrict__ k,
    const float* __restrict__ v, float* __restrict__ o)
{
    extern __shared__ float smem[];
    float* sQ = smem;
    float* sK = sQ + 64 * 128;
    float* sV = sK + 64 * 129;
    float* sP = sV + 64 * 128;

    const int qi = blockIdx.x;
    const int bh = blockIdx.y;
    const int b  = bh / HH;
    const int h  = bh % HH;
    const int kvh = h / GG;
    const int t0 = qi * 64;

    const int tid  = threadIdx.x;
    const int warp = tid >> 5;
    const int lane = tid & 31;

    const float scale = 0.08838834764831845f;

    for (int idx = tid; idx < 64 * 128; idx += 256) {
        int r = idx >> 7, c = idx & 127;
        sQ[idx] = q[(size_t)(b * TT + t0 + r) * (HH * DD) + h * DD + c] * scale;
    }

    float m_i[8], l_i[8], oa[8][4];
#pragma unroll
    for (int rr = 0; rr < 8; rr++) {
        m_i[rr] = -1e30f; l_i[rr] = 0.f;
#pragma unroll
        for (int j = 0; j < 4; j++) oa[rr][j] = 0.f;
    }

    for (int jt = 0; jt <= qi; jt++) {
        __syncthreads();

        for (int idx = tid; idx < 64 * 128; idx += 256) {
            int r = idx >> 7, c = idx & 127;
            size_t gofs = (size_t)(b * TT + jt * 64 + r) * (KVH * DD) + kvh * DD + c;
            sK[r * 129 + c] = k[gofs];
            sV[idx]         = v[gofs];
        }
        __syncthreads();

#pragma unroll
        for (int rr = 0; rr < 8; rr++) {
            int r = warp * 8 + rr;
            const float* qrow = &sQ[r * 128];
            const float* k0p  = &sK[lane * 129];
            const float* k1p  = &sK[(lane + 32) * 129];
            float s0 = 0.f, s1 = 0.f;
#pragma unroll
            for (int d = 0; d < 128; d += 4) {
                float4 qv = *(const float4*)(qrow + d);
                s0 += qv.x * k0p[d]   + qv.y * k0p[d+1] + qv.z * k0p[d+2] + qv.w * k0p[d+3];
                s1 += qv.x * k1p[d]   + qv.y * k1p[d+1] + qv.z * k1p[d+2] + qv.w * k1p[d+3];
            }

            int qglob = t0 + r;
            if (jt * 64 + lane      > qglob) s0 = -1e30f;
            if (jt * 64 + lane + 32 > qglob) s1 = -1e30f;

            float mx = fmaxf(s0, s1);
#pragma unroll
            for (int off = 16; off >= 1; off >>= 1)
                mx = fmaxf(mx, __shfl_xor_sync(0xffffffffu, mx, off));

            float m_new = fmaxf(m_i[rr], mx);
            float p0 = __expf(s0 - m_new);
            float p1 = __expf(s1 - m_new);
            float rs = p0 + p1;
#pragma unroll
            for (int off = 16; off >= 1; off >>= 1)
                rs += __shfl_xor_sync(0xffffffffu, rs, off);

            float f = __expf(m_i[rr] - m_new);
            l_i[rr] = l_i[rr] * f + rs;
            m_i[rr] = m_new;
#pragma unroll
            for (int j = 0; j < 4; j++) oa[rr][j] *= f;

            sP[r * 64 + lane]      = p0;
            sP[r * 64 + lane + 32] = p1;
        }
        __syncwarp();

#pragma unroll
        for (int rr = 0; rr < 8; rr++) {
            int r = warp * 8 + rr;
            const float* prow = &sP[r * 64];
            float a0 = oa[rr][0], a1 = oa[rr][1], a2 = oa[rr][2], a3 = oa[rr][3];
            for (int c = 0; c < 64; c++) {
                float p = prow[c];
                float4 vv = *(const float4*)&sV[c * 128 + lane * 4];
                a0 += p * vv.x; a1 += p * vv.y; a2 += p * vv.z; a3 += p * vv.w;
            }
            oa[rr][0] = a0; oa[rr][1] = a1; oa[rr][2] = a2; oa[rr][3] = a3;
        }
    }

#pragma unroll
    for (int rr = 0; rr < 8; rr++) {
        int r = warp * 8 + rr;
        float invl = 1.0f / l_i[rr];
        float* dst = o + (size_t)(b * TT + t0 + r) * (HH * DD) + h * DD;
        float4 ov = make_float4(oa[rr][0] * invl, oa[rr][1] * invl,
                                oa[rr][2] * invl, oa[rr][3] * invl);
        *(float4*)(dst + lane * 4) = ov;
    }
}

// ---------------------------------------------------------------------------
extern "C" void kernel_launch(void* const* d_in, const int* in_sizes, int n_in,
                              void* d_out, int out_size)
{
    const float *x, *Wq, *Wk, *Wv, *Wo;
    if (in_sizes[0] == BB * TT * CC) {
        x  = (const float*)d_in[0];
        Wq = (const float*)d_in[1];
        Wk = (const float*)d_in[2];
        Wv = (const float*)d_in[3];
        Wo = (const float*)d_in[4];
    } else {
        Wk = (const float*)d_in[0];
        Wo = (const float*)d_in[1];
        Wq = (const float*)d_in[2];
        Wv = (const float*)d_in[3];
        x  = (const float*)d_in[4];
    }
    float* out = (float*)d_out;

    float *q, *k, *v, *ao;
    cudaGetSymbolAddress((void**)&q,  g_q);
    cudaGetSymbolAddress((void**)&k,  g_k);
    cudaGetSymbolAddress((void**)&v,  g_v);
    cudaGetSymbolAddress((void**)&ao, g_ao);

    init_tables_kernel<<<(TT * 64 + 255) / 256, 256>>>();

    dim3 blk(256);
    sgemm128_rope_kernel<<<dim3(HH*DD/128,  MROWS/128), blk>>>(x, Wq, q, MROWS, HH*DD,  CC, 1);
    sgemm128_rope_kernel<<<dim3(KVH*DD/128, MROWS/128), blk>>>(x, Wk, k, MROWS, KVH*DD, CC, 1);
    sgemm128_rope_kernel<<<dim3(KVH*DD/128, MROWS/128), blk>>>(x, Wv, v, MROWS, KVH*DD, CC, 0);

    {
        const int smem_bytes = (64*128 + 64*129 + 64*128 + 64*64) * 4;  // 114944
        cudaFuncSetAttribute(attn_kernel,
                             cudaFuncAttributeMaxDynamicSharedMemorySize, smem_bytes);
        attn_kernel<<<dim3(TT/64, BB*HH), 256, smem_bytes>>>(q, k, v, ao);
    }

    sgemm128_rope_kernel<<<dim3(CC/128, MROWS/128), blk>>>(ao, Wo, out, MROWS, CC, CC, 0);
}

// round 11
// speedup vs baseline: 1.4199x; 1.4199x over previous
#include <cuda_runtime.h>
#include <math.h>
#include <cstdint>

// Problem constants
#define BB 4
#define TT 2048
#define CC 2048
#define HH 16
#define KVH 4
#define GG 4
#define DD 128
#define MROWS (BB*TT)          // 8192

#define BK 32
#define PADA 36     // A smem row pitch (words): 32 + 4
#define PADB 136    // B smem row pitch (words): 128 + 8
#define PADC 132    // C staging pitch

// ---------------- scratch (device globals; allocation is forbidden) --------
__device__ float  g_q [(size_t)MROWS * (HH*DD)];
__device__ float  g_k [(size_t)MROWS * (KVH*DD)];
__device__ float  g_v [(size_t)MROWS * (KVH*DD)];
__device__ float  g_ao[(size_t)MROWS * (HH*DD)];
__device__ float2 g_cs[TT][64];                    // cos/sin(t * 10000^(-p/64))

// ---------------------------------------------------------------------------
// Angle table: fp32-rounded angle exactly as jnp would, then double trig.
// ---------------------------------------------------------------------------
__global__ void init_tables_kernel()
{
    int idx = blockIdx.x * blockDim.x + threadIdx.x;   // t*64 + p
    if (idx >= TT * 64) return;
    int t = idx >> 6;
    int p = idx & 63;

    double ex   = (double)p / 64.0;
    float  invf = (float)pow(10000.0, -ex);
    float  ang  = (float)t * invf;
    double c, s;
    sincos((double)ang, &c, &s);
    g_cs[t][p] = make_float2((float)c, (float)s);
}

__device__ __forceinline__ float f2tf32(float x)
{
    uint32_t u;
    asm("cvt.rna.tf32.f32 %0, %1;" : "=r"(u) : "f"(x));
    return __uint_as_float(u);
}

// ---------------------------------------------------------------------------
// tf32 tensor-core GEMM with fused REVERSED-RoPE epilogue (validated round 9):
//   out[p]    =  a0 * cos + a1 * sin
//   out[p+64] =  a1 * cos - a0 * sin
// C[M,N] = A[M,K] @ B[K,N]. 128x128 tile, BK=32, 256 threads (8 warps, 4x2).
// A smem [m][k] pitch 36 (fragment loads conflict-free), B smem [k][n] pitch
// 136 (conflict-free). tf32 conversion on the smem-store path; fp32 accum.
// Epilogue stages C through smem; RoPE pairs (p, p+64) rotated there.
// ---------------------------------------------------------------------------
__global__ __launch_bounds__(256) void gemm_tf32_rope_kernel(
    const float* __restrict__ A, const float* __restrict__ B,
    float* __restrict__ C, int M, int N, int K, int rope)
{
    extern __shared__ float sm[];
    float* As = sm;                                   // 2 * 128 * PADA
    float* Bs = sm + 2 * 128 * PADA;                  // 2 * 32  * PADB
    float* Cs = sm + 2 * 128 * PADA + 2 * 32 * PADB;  // 128 * PADC

    const int tid  = threadIdx.x;
    const int lane = tid & 31;
    const int warp = tid >> 5;
    const int wm = warp >> 1;          // 0..3  (M)
    const int wn = warp & 1;           // 0..1  (N)
    const int bm = blockIdx.y * 128;
    const int bn = blockIdx.x * 128;

    const int nst = K / BK;

    float4 pa[4], pb[4];
    float acc[2][8][4];
#pragma unroll
    for (int mt = 0; mt < 2; mt++)
#pragma unroll
        for (int nt = 0; nt < 8; nt++)
#pragma unroll
            for (int c = 0; c < 4; c++) acc[mt][nt][c] = 0.f;

    // ---- prologue: stage 0 ----
    {
        const float* Ab = A + (size_t)bm * K;
        const float* Bb = B + bn;
#pragma unroll
        for (int j = 0; j < 4; j++) {
            int ia = tid + j * 256;                   // A: 128x32 -> 1024 float4
            pa[j] = *(const float4*)(Ab + (size_t)(ia >> 3) * K + (ia & 7) * 4);
            pb[j] = *(const float4*)(Bb + (size_t)(ia >> 5) * N + (ia & 31) * 4);
        }
#pragma unroll
        for (int j = 0; j < 4; j++) {
            int ia = tid + j * 256;
            float* ap = As + (ia >> 3) * PADA + (ia & 7) * 4;
            *(float4*)ap = make_float4(f2tf32(pa[j].x), f2tf32(pa[j].y),
                                       f2tf32(pa[j].z), f2tf32(pa[j].w));
            float* bp = Bs + (ia >> 5) * PADB + (ia & 31) * 4;
            *(float4*)bp = make_float4(f2tf32(pb[j].x), f2tf32(pb[j].y),
                                       f2tf32(pb[j].z), f2tf32(pb[j].w));
        }
    }
    __syncthreads();

    for (int s = 0; s < nst; s++) {
        // ---- prefetch next stage into registers ----
        if (s + 1 < nst) {
            const float* Ab = A + (size_t)bm * K + (s + 1) * BK;
            const float* Bb = B + (size_t)(s + 1) * BK * N + bn;
#pragma unroll
            for (int j = 0; j < 4; j++) {
                int ia = tid + j * 256;
                pa[j] = *(const float4*)(Ab + (size_t)(ia >> 3) * K + (ia & 7) * 4);
                pb[j] = *(const float4*)(Bb + (size_t)(ia >> 5) * N + (ia & 31) * 4);
            }
        }

        // ---- compute on current buffer ----
        {
            const float* Ab = As + (s & 1) * 128 * PADA;
            const float* Bb = Bs + (s & 1) * 32 * PADB;
#pragma unroll
            for (int kk = 0; kk < 4; kk++) {
                uint32_t af[2][4], bf[8][2];
                const int k0 = kk * 8;
                const int arow = wm * 32 + (lane >> 2);
                const int acol = k0 + (lane & 3);
#pragma unroll
                for (int mt = 0; mt < 2; mt++) {
                    const float* ap = Ab + (size_t)(arow + mt * 16) * PADA + acol;
                    af[mt][0] = __float_as_uint(ap[0]);
                    af[mt][1] = __float_as_uint(ap[8 * PADA]);
                    af[mt][2] = __float_as_uint(ap[4]);
                    af[mt][3] = __float_as_uint(ap[8 * PADA + 4]);
                }
                const int bk  = k0 + (lane & 3);
                const int bn0 = wn * 64 + (lane >> 2);
#pragma unroll
                for (int nt = 0; nt < 8; nt++) {
                    const float* bp = Bb + (size_t)bk * PADB + bn0 + nt * 8;
                    bf[nt][0] = __float_as_uint(bp[0]);
                    bf[nt][1] = __float_as_uint(bp[4 * PADB]);
                }
#pragma unroll
                for (int mt = 0; mt < 2; mt++)
#pragma unroll
                    for (int nt = 0; nt < 8; nt++)
                        asm volatile(
                            "mma.sync.aligned.m16n8k8.row.col.f32.tf32.tf32.f32 "
                            "{%0,%1,%2,%3}, {%4,%5,%6,%7}, {%8,%9}, {%0,%1,%2,%3};"
                            : "+f"(acc[mt][nt][0]), "+f"(acc[mt][nt][1]),
                              "+f"(acc[mt][nt][2]), "+f"(acc[mt][nt][3])
                            : "r"(af[mt][0]), "r"(af[mt][1]),
                              "r"(af[mt][2]), "r"(af[mt][3]),
                              "r"(bf[nt][0]), "r"(bf[nt][1]));
            }
        }

        // ---- store prefetched stage into the other buffer ----
        if (s + 1 < nst) {
            float* Ad = As + ((s + 1) & 1) * 128 * PADA;
            float* Bd = Bs + ((s + 1) & 1) * 32 * PADB;
#pragma unroll
            for (int j = 0; j < 4; j++) {
                int ia = tid + j * 256;
                float* ap = Ad + (ia >> 3) * PADA + (ia & 7) * 4;
                *(float4*)ap = make_float4(f2tf32(pa[j].x), f2tf32(pa[j].y),
                                           f2tf32(pa[j].z), f2tf32(pa[j].w));
                float* bp = Bd + (ia >> 5) * PADB + (ia & 31) * 4;
                *(float4*)bp = make_float4(f2tf32(pb[j].x), f2tf32(pb[j].y),
                                           f2tf32(pb[j].z), f2tf32(pb[j].w));
            }
        }
        __syncthreads();
    }

    // ---- epilogue: stage through smem, then (optionally) rotate and store --
#pragma unroll
    for (int mt = 0; mt < 2; mt++)
#pragma unroll
        for (int nt = 0; nt < 8; nt++) {
            int r0 = wm * 32 + mt * 16 + (lane >> 2);
            int c0 = wn * 64 + nt * 8 + (lane & 3) * 2;
            *(float2*)&Cs[r0 * PADC + c0]       = make_float2(acc[mt][nt][0], acc[mt][nt][1]);
            *(float2*)&Cs[(r0 + 8) * PADC + c0] = make_float2(acc[mt][nt][2], acc[mt][nt][3]);
        }
    __syncthreads();

    if (rope) {
#pragma unroll
        for (int j = 0; j < 32; j++) {
            int idx = tid + j * 256;       // 128 rows * 64 pairs
            int row = idx >> 6, p = idx & 63;
            int t = (bm + row) & (TT - 1);
            float2 cs = g_cs[t][p];
            float a0 = Cs[row * PADC + p];
            float a1 = Cs[row * PADC + p + 64];
            float* crow = C + (size_t)(bm + row) * N + bn;
            crow[p]      = a0 * cs.x + a1 * cs.y;   // reversed rotation
            crow[p + 64] = a1 * cs.x - a0 * cs.y;
        }
    } else {
#pragma unroll
        for (int j = 0; j < 16; j++) {
            int idx = tid + j * 256;       // 128 rows * 32 float4
            int row = idx >> 5, c4 = idx & 31;
            *(float4*)(C + (size_t)(bm + row) * N + bn + c4 * 4) =
                *(float4*)&Cs[row * PADC + c4 * 4];
        }
    }
}

// ---------------------------------------------------------------------------
// Attention (causal, GQA), warp-private formulation. UNCHANGED (validated).
// ---------------------------------------------------------------------------
__global__ __launch_bounds__(256) void attn_kernel(
    const float* __restrict__ q, const float* __restrict__ k,
    const float* __restrict__ v, float* __restrict__ o)
{
    extern __shared__ float smem[];
    float* sQ = smem;
    float* sK = sQ + 64 * 128;
    float* sV = sK + 64 * 129;
    float* sP = sV + 64 * 128;

    const int qi = blockIdx.x;
    const int bh = blockIdx.y;
    const int b  = bh / HH;
    const int h  = bh % HH;
    const int kvh = h / GG;
    const int t0 = qi * 64;

    const int tid  = threadIdx.x;
    const int warp = tid >> 5;
    const int lane = tid & 31;

    const float scale = 0.08838834764831845f;

    for (int idx = tid; idx < 64 * 128; idx += 256) {
        int r = idx >> 7, c = idx & 127;
        sQ[idx] = q[(size_t)(b * TT + t0 + r) * (HH * DD) + h * DD + c] * scale;
    }

    float m_i[8], l_i[8], oa[8][4];
#pragma unroll
    for (int rr = 0; rr < 8; rr++) {
        m_i[rr] = -1e30f; l_i[rr] = 0.f;
#pragma unroll
        for (int j = 0; j < 4; j++) oa[rr][j] = 0.f;
    }

    for (int jt = 0; jt <= qi; jt++) {
        __syncthreads();

        for (int idx = tid; idx < 64 * 128; idx += 256) {
            int r = idx >> 7, c = idx & 127;
            size_t gofs = (size_t)(b * TT + jt * 64 + r) * (KVH * DD) + kvh * DD + c;
            sK[r * 129 + c] = k[gofs];
            sV[idx]         = v[gofs];
        }
        __syncthreads();

#pragma unroll
        for (int rr = 0; rr < 8; rr++) {
            int r = warp * 8 + rr;
            const float* qrow = &sQ[r * 128];
            const float* k0p  = &sK[lane * 129];
            const float* k1p  = &sK[(lane + 32) * 129];
            float s0 = 0.f, s1 = 0.f;
#pragma unroll
            for (int d = 0; d < 128; d += 4) {
                float4 qv = *(const float4*)(qrow + d);
                s0 += qv.x * k0p[d]   + qv.y * k0p[d+1] + qv.z * k0p[d+2] + qv.w * k0p[d+3];
                s1 += qv.x * k1p[d]   + qv.y * k1p[d+1] + qv.z * k1p[d+2] + qv.w * k1p[d+3];
            }

            int qglob = t0 + r;
            if (jt * 64 + lane      > qglob) s0 = -1e30f;
            if (jt * 64 + lane + 32 > qglob) s1 = -1e30f;

            float mx = fmaxf(s0, s1);
#pragma unroll
            for (int off = 16; off >= 1; off >>= 1)
                mx = fmaxf(mx, __shfl_xor_sync(0xffffffffu, mx, off));

            float m_new = fmaxf(m_i[rr], mx);
            float p0 = __expf(s0 - m_new);
            float p1 = __expf(s1 - m_new);
            float rs = p0 + p1;
#pragma unroll
            for (int off = 16; off >= 1; off >>= 1)
                rs += __shfl_xor_sync(0xffffffffu, rs, off);

            float f = __expf(m_i[rr] - m_new);
            l_i[rr] = l_i[rr] * f + rs;
            m_i[rr] = m_new;
#pragma unroll
            for (int j = 0; j < 4; j++) oa[rr][j] *= f;

            sP[r * 64 + lane]      = p0;
            sP[r * 64 + lane + 32] = p1;
        }
        __syncwarp();

#pragma unroll
        for (int rr = 0; rr < 8; rr++) {
            int r = warp * 8 + rr;
            const float* prow = &sP[r * 64];
            float a0 = oa[rr][0], a1 = oa[rr][1], a2 = oa[rr][2], a3 = oa[rr][3];
            for (int c = 0; c < 64; c++) {
                float p = prow[c];
                float4 vv = *(const float4*)&sV[c * 128 + lane * 4];
                a0 += p * vv.x; a1 += p * vv.y; a2 += p * vv.z; a3 += p * vv.w;
            }
            oa[rr][0] = a0; oa[rr][1] = a1; oa[rr][2] = a2; oa[rr][3] = a3;
        }
    }

#pragma unroll
    for (int rr = 0; rr < 8; rr++) {
        int r = warp * 8 + rr;
        float invl = 1.0f / l_i[rr];
        float* dst = o + (size_t)(b * TT + t0 + r) * (HH * DD) + h * DD;
        float4 ov = make_float4(oa[rr][0] * invl, oa[rr][1] * invl,
                                oa[rr][2] * invl, oa[rr][3] * invl);
        *(float4*)(dst + lane * 4) = ov;
    }
}

// ---------------------------------------------------------------------------
extern "C" void kernel_launch(void* const* d_in, const int* in_sizes, int n_in,
                              void* d_out, int out_size)
{
    const float *x, *Wq, *Wk, *Wv, *Wo;
    if (in_sizes[0] == BB * TT * CC) {
        x  = (const float*)d_in[0];
        Wq = (const float*)d_in[1];
        Wk = (const float*)d_in[2];
        Wv = (const float*)d_in[3];
        Wo = (const float*)d_in[4];
    } else {
        Wk = (const float*)d_in[0];
        Wo = (const float*)d_in[1];
        Wq = (const float*)d_in[2];
        Wv = (const float*)d_in[3];
        x  = (const float*)d_in[4];
    }
    float* out = (float*)d_out;

    float *q, *k, *v, *ao;
    cudaGetSymbolAddress((void**)&q,  g_q);
    cudaGetSymbolAddress((void**)&k,  g_k);
    cudaGetSymbolAddress((void**)&v,  g_v);
    cudaGetSymbolAddress((void**)&ao, g_ao);

    init_tables_kernel<<<(TT * 64 + 255) / 256, 256>>>();

    const int gemm_smem = (2*128*PADA + 2*32*PADB + 128*PADC) * 4;  // 139264 B
    cudaFuncSetAttribute(gemm_tf32_rope_kernel,
                         cudaFuncAttributeMaxDynamicSharedMemorySize, gemm_smem);

    dim3 blk(256);
    gemm_tf32_rope_kernel<<<dim3(HH*DD/128,  MROWS/128), blk, gemm_smem>>>(x, Wq, q, MROWS, HH*DD,  CC, 1);
    gemm_tf32_rope_kernel<<<dim3(KVH*DD/128, MROWS/128), blk, gemm_smem>>>(x, Wk, k, MROWS, KVH*DD, CC, 1);
    gemm_tf32_rope_kernel<<<dim3(KVH*DD/128, MROWS/128), blk, gemm_smem>>>(x, Wv, v, MROWS, KVH*DD, CC, 0);

    {
        const int smem_bytes = (64*128 + 64*129 + 64*128 + 64*64) * 4;  // 114944
        cudaFuncSetAttribute(attn_kernel,
                             cudaFuncAttributeMaxDynamicSharedMemorySize, smem_bytes);
        attn_kernel<<<dim3(TT/64, BB*HH), 256, smem_bytes>>>(q, k, v, ao);
    }

    gemm_tf32_rope_kernel<<<dim3(CC/128, MROWS/128), blk, gemm_smem>>>(ao, Wo, out, MROWS, CC, CC, 0);
}